// round 2
// baseline (speedup 1.0000x reference)
#include <cuda_runtime.h>

// ---------------------------------------------------------------------------
// AnomalyAttention: B=16, N=1024, C_IN=C_OUT=256
// Outputs concatenated: Z [B,N,C], P [B,N,N], S [B,N,N]
// ---------------------------------------------------------------------------

#define BB 16
#define NN 1024
#define CC 256

static const long long OFF_Z = 0;
static const long long OFF_P = (long long)BB * NN * CC;              // 4,194,304
static const long long OFF_S = OFF_P + (long long)BB * NN * NN;      // 20,971,520

// Scratch (device globals — no allocation allowed)
__device__ float g_Q[(size_t)BB * NN * CC];
__device__ float g_K[(size_t)BB * NN * CC];
__device__ float g_V[(size_t)BB * NN * CC];
__device__ float g_scores[(size_t)BB * NN * NN];

// ---------------------------------------------------------------------------
// Tiled SGEMM: C = alpha * A * op(B)
//   A: [M,K] row-major. TRANS_B=false: B [K,N] row-major. true: B [N,K] (A*B^T).
//   128x128 tile, BK=8, 256 threads, 8x8 per-thread microtile.
//   All dims assumed multiples of 128 (holds for every call here).
// ---------------------------------------------------------------------------
template <bool TRANS_B>
__global__ __launch_bounds__(256) void sgemm_kernel(
    const float* __restrict__ A, const float* __restrict__ B, float* __restrict__ C,
    int M, int N, int K, float alpha,
    long long sA, long long sB, long long sC)
{
    constexpr int BM = 128, BN = 128, BK = 8, TM = 8, TN = 8;
    __shared__ float As[BK][BM];
    __shared__ float Bs[BK][BN];

    A += (long long)blockIdx.z * sA;
    B += (long long)blockIdx.z * sB;
    C += (long long)blockIdx.z * sC;

    const int brow = blockIdx.y * BM;
    const int bcol = blockIdx.x * BN;
    const int tid = threadIdx.x;
    const int tx = tid & 15;       // 0..15  -> N dir
    const int ty = tid >> 4;       // 0..15  -> M dir

    // A tile load mapping: 128 rows x 8 k-cols = 256 float4
    const int aRow = tid >> 1;           // 0..127
    const int aK4  = (tid & 1) * 4;      // 0 or 4
    // B tile load mapping (no trans): 8 k-rows x 128 cols = 256 float4
    const int bK  = tid >> 5;            // 0..7
    const int bC4 = (tid & 31) * 4;      // 0..124

    float acc[TM][TN] = {};

    for (int k0 = 0; k0 < K; k0 += BK) {
        float4 a4 = *reinterpret_cast<const float4*>(
            &A[(long long)(brow + aRow) * K + k0 + aK4]);
        As[aK4 + 0][aRow] = a4.x;
        As[aK4 + 1][aRow] = a4.y;
        As[aK4 + 2][aRow] = a4.z;
        As[aK4 + 3][aRow] = a4.w;

        if (TRANS_B) {
            float4 b4 = *reinterpret_cast<const float4*>(
                &B[(long long)(bcol + aRow) * K + k0 + aK4]);
            Bs[aK4 + 0][aRow] = b4.x;
            Bs[aK4 + 1][aRow] = b4.y;
            Bs[aK4 + 2][aRow] = b4.z;
            Bs[aK4 + 3][aRow] = b4.w;
        } else {
            float4 b4 = *reinterpret_cast<const float4*>(
                &B[(long long)(k0 + bK) * N + bcol + bC4]);
            *reinterpret_cast<float4*>(&Bs[bK][bC4]) = b4;
        }
        __syncthreads();

        #pragma unroll
        for (int k = 0; k < BK; k++) {
            float a[TM], b[TN];
            *reinterpret_cast<float4*>(&a[0]) = *reinterpret_cast<const float4*>(&As[k][ty * TM]);
            *reinterpret_cast<float4*>(&a[4]) = *reinterpret_cast<const float4*>(&As[k][ty * TM + 4]);
            *reinterpret_cast<float4*>(&b[0]) = *reinterpret_cast<const float4*>(&Bs[k][tx * TN]);
            *reinterpret_cast<float4*>(&b[4]) = *reinterpret_cast<const float4*>(&Bs[k][tx * TN + 4]);
            #pragma unroll
            for (int i = 0; i < TM; i++)
                #pragma unroll
                for (int j = 0; j < TN; j++)
                    acc[i][j] += a[i] * b[j];
        }
        __syncthreads();
    }

    #pragma unroll
    for (int i = 0; i < TM; i++) {
        #pragma unroll
        for (int j = 0; j < TN; j += 4) {
            float4 v = make_float4(acc[i][j] * alpha, acc[i][j + 1] * alpha,
                                   acc[i][j + 2] * alpha, acc[i][j + 3] * alpha);
            *reinterpret_cast<float4*>(
                &C[(long long)(brow + ty * TM + i) * N + bcol + tx * TN + j]) = v;
        }
    }
}

// ---------------------------------------------------------------------------
// Softmax over batch dim (axis=0): for each (n,m), softmax across the 16 b's.
// One thread per (n,m). scores [B,N,N] -> S at out+OFF_S.
// ---------------------------------------------------------------------------
__global__ __launch_bounds__(256) void batch_softmax_kernel(
    const float* __restrict__ scores, float* __restrict__ S)
{
    size_t idx = (size_t)blockIdx.x * blockDim.x + threadIdx.x;  // 0 .. N*N-1
    float v[BB];
    float mx = -1e30f;
    #pragma unroll
    for (int b = 0; b < BB; b++) {
        v[b] = scores[(size_t)b * NN * NN + idx];
        mx = fmaxf(mx, v[b]);
    }
    float s = 0.f;
    #pragma unroll
    for (int b = 0; b < BB; b++) {
        v[b] = __expf(v[b] - mx);
        s += v[b];
    }
    float inv = 1.0f / s;
    #pragma unroll
    for (int b = 0; b < BB; b++)
        S[(size_t)b * NN * NN + idx] = v[b] * inv;
}

// ---------------------------------------------------------------------------
// P kernel: one block per (b,n) row.
//   sigma   = |dot(x[row,:], W_sigma)|
//   gaussian[m] = |n-m| + sigma*eps[row,m]
//   rowsum  = A(n) + sigma * sum(eps[row,:]),  A(n) = closed-form sum of |n-m|
//   P[row,m] = gaussian[m] / rowsum
// Single pass over eps (held in registers).
// ---------------------------------------------------------------------------
__global__ __launch_bounds__(256) void p_kernel(
    const float* __restrict__ x, const float* __restrict__ Wsig,
    const float* __restrict__ eps, float* __restrict__ P)
{
    const int row = blockIdx.x;       // b*N + n
    const int n = row & (NN - 1);
    const int tid = threadIdx.x;
    __shared__ float red[8];

    // --- sigma = |x[row,:] . Wsig| ---
    float part = x[(size_t)row * CC + tid] * Wsig[tid];
    #pragma unroll
    for (int o = 16; o > 0; o >>= 1) part += __shfl_xor_sync(0xffffffffu, part, o);
    if ((tid & 31) == 0) red[tid >> 5] = part;
    __syncthreads();
    float sig = red[0] + red[1] + red[2] + red[3] + red[4] + red[5] + red[6] + red[7];
    sig = fabsf(sig);
    __syncthreads();  // protect red[] before reuse

    // --- eps row: 4 per thread ---
    float4 e = *reinterpret_cast<const float4*>(&eps[(size_t)row * NN + tid * 4]);
    float ps = e.x + e.y + e.z + e.w;
    #pragma unroll
    for (int o = 16; o > 0; o >>= 1) ps += __shfl_xor_sync(0xffffffffu, ps, o);
    if ((tid & 31) == 0) red[tid >> 5] = ps;
    __syncthreads();
    float sum_eps = red[0] + red[1] + red[2] + red[3] + red[4] + red[5] + red[6] + red[7];

    // A(n) = sum_m |n-m| = n(n+1)/2 + (N-1-n)(N-n)/2
    float An = 0.5f * ((float)n * (float)(n + 1) +
                       (float)(NN - 1 - n) * (float)(NN - n));
    float inv = 1.0f / (An + sig * sum_eps);

    int m0 = tid * 4;
    float4 o4;
    o4.x = (fabsf((float)(n - (m0 + 0))) + sig * e.x) * inv;
    o4.y = (fabsf((float)(n - (m0 + 1))) + sig * e.y) * inv;
    o4.z = (fabsf((float)(n - (m0 + 2))) + sig * e.z) * inv;
    o4.w = (fabsf((float)(n - (m0 + 3))) + sig * e.w) * inv;
    *reinterpret_cast<float4*>(&P[(size_t)row * NN + m0]) = o4;
}

// ---------------------------------------------------------------------------
extern "C" void kernel_launch(void* const* d_in, const int* in_sizes, int n_in,
                              void* d_out, int out_size)
{
    const float* x   = (const float*)d_in[0];
    const float* Wq  = (const float*)d_in[1];
    const float* Wk  = (const float*)d_in[2];
    const float* Wv  = (const float*)d_in[3];
    const float* Ws  = (const float*)d_in[4];
    const float* eps = (const float*)d_in[5];
    float* out = (float*)d_out;

    float *Q, *K, *V, *scores;
    cudaGetSymbolAddress((void**)&Q, g_Q);
    cudaGetSymbolAddress((void**)&K, g_K);
    cudaGetSymbolAddress((void**)&V, g_V);
    cudaGetSymbolAddress((void**)&scores, g_scores);

    const int M_qkv = BB * NN;  // 16384

    // 1) Q/K/V = x @ W  (M=16384, N=256, K=256)
    {
        dim3 grid(CC / 128, M_qkv / 128, 1);
        sgemm_kernel<false><<<grid, 256>>>(x, Wq, Q, M_qkv, CC, CC, 1.0f, 0, 0, 0);
        sgemm_kernel<false><<<grid, 256>>>(x, Wk, K, M_qkv, CC, CC, 1.0f, 0, 0, 0);
        sgemm_kernel<false><<<grid, 256>>>(x, Wv, V, M_qkv, CC, CC, 1.0f, 0, 0, 0);
    }

    // 2) scores_b = Q_b @ K_b^T / 16   (per batch, M=N=1024, K=256)
    {
        dim3 grid(NN / 128, NN / 128, BB);
        sgemm_kernel<true><<<grid, 256>>>(Q, K, scores, NN, NN, CC, 1.0f / 16.0f,
                                          (long long)NN * CC, (long long)NN * CC,
                                          (long long)NN * NN);
    }

    // 3) S = softmax over batch dim, written straight into the output slot
    {
        dim3 grid((NN * NN) / 256);
        batch_softmax_kernel<<<grid, 256>>>(scores, out + OFF_S);
    }

    // 4) Z_b = S_b @ V_b   (M=1024, N=256, K=1024)
    {
        dim3 grid(CC / 128, NN / 128, BB);
        sgemm_kernel<false><<<grid, 256>>>(out + OFF_S, V, out + OFF_Z, NN, CC, NN, 1.0f,
                                           (long long)NN * NN, (long long)NN * CC,
                                           (long long)NN * CC);
    }

    // 5) P (independent of the attention path)
    {
        p_kernel<<<BB * NN, 256>>>(x, Ws, eps, out + OFF_P);
    }
}

// round 4
// speedup vs baseline: 2.7348x; 2.7348x over previous
#include <cuda_runtime.h>
#include <cstdint>

// ---------------------------------------------------------------------------
// AnomalyAttention B=16, N=1024, C=256 — mma.sync tf32 GEMMs (portable ISA)
// Outputs: Z [B,N,C] | P [B,N,N] | S [B,N,N]
// ---------------------------------------------------------------------------

#define BB 16
#define NN 1024
#define CC 256

static const long long OFF_Z = 0;
static const long long OFF_P = (long long)BB * NN * CC;
static const long long OFF_S = OFF_P + (long long)BB * NN * NN;

// Scratch (device globals — no runtime allocation allowed)
__device__ float g_xr[(size_t)BB * NN * CC];          // tf32-rounded x
__device__ float g_QKV[(size_t)3 * BB * NN * CC];     // Q|K|V (tf32-rounded)
__device__ float g_Vt[(size_t)BB * NN * CC];          // V^T per batch [C,N]
__device__ float g_Wt[(size_t)3 * CC * CC];           // W^T (tf32-rounded)
__device__ float g_scores[(size_t)BB * NN * NN];      // scores, then rounded S

// ---------------------------------------------------------------------------
__device__ __forceinline__ uint32_t smem_u32(const void* p) {
    uint32_t a;
    asm("{ .reg .u64 t; cvta.to.shared.u64 t, %1; cvt.u32.u64 %0, t; }"
        : "=r"(a) : "l"(p));
    return a;
}
__device__ __forceinline__ float tf32r(float x) {
    float y; asm("cvt.rna.tf32.f32 %0, %1;" : "=f"(y) : "f"(x)); return y;
}

// ---------------------------------------------------------------------------
// mma.sync tf32 GEMM: C = alpha * A * B^T
//   A [M,K] K-major, B [N,K] K-major, dims % 128 == 0, K % 32 == 0.
//   CTA: 128x128 tile, 256 threads = 8 warps (2 M x 4 N), warp tile 64x32.
//   BK=32 double-buffered cp.async; smem rows padded to 36 floats
//   (bank = (4*(lane>>2) + (lane&3)) % 32 — bijective, conflict-free).
// ---------------------------------------------------------------------------
template <bool ROUND_OUT>
__global__ __launch_bounds__(256, 2) void mma_abt(
    const float* __restrict__ A, const float* __restrict__ B, float* __restrict__ C,
    int K, int ldc, float alpha, long long sA, long long sB, long long sC)
{
    constexpr int BM = 128, BK = 32, PAD = 36;
    extern __shared__ float sm[];
    float* As = sm;                    // [2][BM][PAD]
    float* Bs = sm + 2 * BM * PAD;     // [2][BN][PAD]

    A += (long long)blockIdx.z * sA;
    B += (long long)blockIdx.z * sB;
    C += (long long)blockIdx.z * sC;

    const int tid = threadIdx.x, lane = tid & 31, wid = tid >> 5;
    const int wm = wid >> 2, wn = wid & 3;          // 2 x 4 warp grid
    const int g = lane >> 2, t = lane & 3;
    const long long arow0 = (long long)blockIdx.y * BM;
    const long long brow0 = (long long)blockIdx.x * BM;

    // cp.async staging: 1024 16B-chunks per matrix per stage; 4 per thread each
    auto issue = [&](int j) {
        const int buf = (j & 1) * BM * PAD;
        #pragma unroll
        for (int i = 0; i < 4; i++) {
            const int ch  = tid + 256 * i;
            const int row = ch >> 3, c16 = ch & 7;
            const uint32_t da = smem_u32(&As[buf + row * PAD + c16 * 4]);
            const float* pa = A + (arow0 + row) * K + (long long)j * BK + c16 * 4;
            asm volatile("cp.async.cg.shared.global [%0], [%1], 16;"
                         :: "r"(da), "l"(pa) : "memory");
            const uint32_t db = smem_u32(&Bs[buf + row * PAD + c16 * 4]);
            const float* pb = B + (brow0 + row) * K + (long long)j * BK + c16 * 4;
            asm volatile("cp.async.cg.shared.global [%0], [%1], 16;"
                         :: "r"(db), "l"(pb) : "memory");
        }
        asm volatile("cp.async.commit_group;" ::: "memory");
    };

    float acc[4][4][4];
    #pragma unroll
    for (int i = 0; i < 4; i++)
        #pragma unroll
        for (int jn = 0; jn < 4; jn++)
            #pragma unroll
            for (int r = 0; r < 4; r++) acc[i][jn][r] = 0.f;

    const int nch = K / BK;
    issue(0);

    for (int j = 0; j < nch; j++) {
        if (j + 1 < nch) {
            issue(j + 1);
            asm volatile("cp.async.wait_group 1;" ::: "memory");
        } else {
            asm volatile("cp.async.wait_group 0;" ::: "memory");
        }
        __syncthreads();

        const float* a_ = &As[(j & 1) * BM * PAD];
        const float* b_ = &Bs[(j & 1) * BM * PAD];

        #pragma unroll
        for (int ks = 0; ks < 4; ks++) {
            uint32_t af[4][4], bf[4][2];
            #pragma unroll
            for (int mt = 0; mt < 4; mt++) {
                const int r = wm * 64 + mt * 16 + g;
                const int c = ks * 8 + t;
                af[mt][0] = __float_as_uint(a_[r * PAD + c]);
                af[mt][1] = __float_as_uint(a_[(r + 8) * PAD + c]);
                af[mt][2] = __float_as_uint(a_[r * PAD + c + 4]);
                af[mt][3] = __float_as_uint(a_[(r + 8) * PAD + c + 4]);
            }
            #pragma unroll
            for (int nt = 0; nt < 4; nt++) {
                const int n = wn * 32 + nt * 8 + g;
                bf[nt][0] = __float_as_uint(b_[n * PAD + ks * 8 + t]);
                bf[nt][1] = __float_as_uint(b_[n * PAD + ks * 8 + t + 4]);
            }
            #pragma unroll
            for (int mt = 0; mt < 4; mt++)
                #pragma unroll
                for (int nt = 0; nt < 4; nt++)
                    asm volatile(
                        "mma.sync.aligned.m16n8k8.row.col.f32.tf32.tf32.f32 "
                        "{%0,%1,%2,%3}, {%4,%5,%6,%7}, {%8,%9}, {%0,%1,%2,%3};"
                        : "+f"(acc[mt][nt][0]), "+f"(acc[mt][nt][1]),
                          "+f"(acc[mt][nt][2]), "+f"(acc[mt][nt][3])
                        : "r"(af[mt][0]), "r"(af[mt][1]), "r"(af[mt][2]), "r"(af[mt][3]),
                          "r"(bf[nt][0]), "r"(bf[nt][1]));
        }
        __syncthreads();
    }

    // epilogue: c0,c1 at (row g, cols 2t,2t+1); c2,c3 at row g+8
    #pragma unroll
    for (int mt = 0; mt < 4; mt++) {
        const long long gr = arow0 + wm * 64 + mt * 16 + g;
        #pragma unroll
        for (int nt = 0; nt < 4; nt++) {
            const long long gc = brow0 + wn * 32 + nt * 8 + 2 * t;
            float2 v0 = make_float2(acc[mt][nt][0] * alpha, acc[mt][nt][1] * alpha);
            float2 v1 = make_float2(acc[mt][nt][2] * alpha, acc[mt][nt][3] * alpha);
            if (ROUND_OUT) {
                v0.x = tf32r(v0.x); v0.y = tf32r(v0.y);
                v1.x = tf32r(v1.x); v1.y = tf32r(v1.y);
            }
            *reinterpret_cast<float2*>(&C[gr * ldc + gc])       = v0;
            *reinterpret_cast<float2*>(&C[(gr + 8) * ldc + gc]) = v1;
        }
    }
}

// ---------------------------------------------------------------------------
// elementwise tf32 rounding pass (x -> g_xr)
// ---------------------------------------------------------------------------
__global__ __launch_bounds__(256) void round_kernel(const float* __restrict__ in,
                                                    float* __restrict__ out)
{
    size_t i = ((size_t)blockIdx.x * blockDim.x + threadIdx.x) * 4;
    float4 v = *reinterpret_cast<const float4*>(&in[i]);
    v.x = tf32r(v.x); v.y = tf32r(v.y); v.z = tf32r(v.z); v.w = tf32r(v.w);
    *reinterpret_cast<float4*>(&out[i]) = v;
}

// ---------------------------------------------------------------------------
// transpose with tf32 rounding: in [R, Ccols] -> out [Ccols, R]
// ---------------------------------------------------------------------------
__global__ __launch_bounds__(256) void transpose_kernel(
    const float* __restrict__ in, float* __restrict__ out,
    int R, int Ccols, long long sIn, long long sOut)
{
    __shared__ float tbuf[32][33];
    in  += (long long)blockIdx.z * sIn;
    out += (long long)blockIdx.z * sOut;
    const int r0 = blockIdx.y * 32, c0 = blockIdx.x * 32;
    const int tx = threadIdx.x, ty = threadIdx.y;
    #pragma unroll
    for (int i = ty; i < 32; i += 8)
        tbuf[i][tx] = in[(long long)(r0 + i) * Ccols + c0 + tx];
    __syncthreads();
    #pragma unroll
    for (int i = ty; i < 32; i += 8)
        out[(long long)(c0 + i) * R + r0 + tx] = tf32r(tbuf[tx][i]);
}

// ---------------------------------------------------------------------------
// softmax over batch dim (axis=0); exact S -> out, rounded S -> scores
// ---------------------------------------------------------------------------
__global__ __launch_bounds__(256) void batch_softmax_kernel(
    float* __restrict__ scores, float* __restrict__ S)
{
    size_t idx = (size_t)blockIdx.x * blockDim.x + threadIdx.x;
    float v[BB];
    float mx = -1e30f;
    #pragma unroll
    for (int b = 0; b < BB; b++) {
        v[b] = scores[(size_t)b * NN * NN + idx];
        mx = fmaxf(mx, v[b]);
    }
    float s = 0.f;
    #pragma unroll
    for (int b = 0; b < BB; b++) { v[b] = __expf(v[b] - mx); s += v[b]; }
    const float inv = 1.0f / s;
    #pragma unroll
    for (int b = 0; b < BB; b++) {
        float sv = v[b] * inv;
        S[(size_t)b * NN * NN + idx] = sv;
        scores[(size_t)b * NN * NN + idx] = tf32r(sv);
    }
}

// ---------------------------------------------------------------------------
// P kernel (fp32 exact): P[row,m] = (|n-m| + sig*eps)/rowsum
// ---------------------------------------------------------------------------
__global__ __launch_bounds__(256) void p_kernel(
    const float* __restrict__ x, const float* __restrict__ Wsig,
    const float* __restrict__ eps, float* __restrict__ P)
{
    const int row = blockIdx.x;
    const int n = row & (NN - 1);
    const int tid = threadIdx.x;
    __shared__ float red[8];

    float part = x[(size_t)row * CC + tid] * Wsig[tid];
    #pragma unroll
    for (int o = 16; o > 0; o >>= 1) part += __shfl_xor_sync(0xffffffffu, part, o);
    if ((tid & 31) == 0) red[tid >> 5] = part;
    __syncthreads();
    float sig = red[0] + red[1] + red[2] + red[3] + red[4] + red[5] + red[6] + red[7];
    sig = fabsf(sig);
    __syncthreads();

    float4 e = *reinterpret_cast<const float4*>(&eps[(size_t)row * NN + tid * 4]);
    float ps = e.x + e.y + e.z + e.w;
    #pragma unroll
    for (int o = 16; o > 0; o >>= 1) ps += __shfl_xor_sync(0xffffffffu, ps, o);
    if ((tid & 31) == 0) red[tid >> 5] = ps;
    __syncthreads();
    float sum_eps = red[0] + red[1] + red[2] + red[3] + red[4] + red[5] + red[6] + red[7];

    float An = 0.5f * ((float)n * (float)(n + 1) +
                       (float)(NN - 1 - n) * (float)(NN - n));
    float inv = 1.0f / (An + sig * sum_eps);

    int m0 = tid * 4;
    float4 o4;
    o4.x = (fabsf((float)(n - (m0 + 0))) + sig * e.x) * inv;
    o4.y = (fabsf((float)(n - (m0 + 1))) + sig * e.y) * inv;
    o4.z = (fabsf((float)(n - (m0 + 2))) + sig * e.z) * inv;
    o4.w = (fabsf((float)(n - (m0 + 3))) + sig * e.w) * inv;
    *reinterpret_cast<float4*>(&P[(size_t)row * NN + m0]) = o4;
}

// ---------------------------------------------------------------------------
extern "C" void kernel_launch(void* const* d_in, const int* in_sizes, int n_in,
                              void* d_out, int out_size)
{
    const float* x   = (const float*)d_in[0];
    const float* Wq  = (const float*)d_in[1];
    const float* Wk  = (const float*)d_in[2];
    const float* Wv  = (const float*)d_in[3];
    const float* Ws  = (const float*)d_in[4];
    const float* eps = (const float*)d_in[5];
    float* out = (float*)d_out;

    float *xr, *QKV, *Vt, *Wt, *scores;
    cudaGetSymbolAddress((void**)&xr, g_xr);
    cudaGetSymbolAddress((void**)&QKV, g_QKV);
    cudaGetSymbolAddress((void**)&Vt, g_Vt);
    cudaGetSymbolAddress((void**)&Wt, g_Wt);
    cudaGetSymbolAddress((void**)&scores, g_scores);

    const int SMEM_SZ = 2 * 2 * 128 * 36 * sizeof(float);   // 73,728 B
    cudaFuncSetAttribute(mma_abt<true>,  cudaFuncAttributeMaxDynamicSharedMemorySize, SMEM_SZ);
    cudaFuncSetAttribute(mma_abt<false>, cudaFuncAttributeMaxDynamicSharedMemorySize, SMEM_SZ);

    const long long QKV_SZ = (long long)BB * NN * CC;

    // 0) round x; transpose+round W's
    round_kernel<<<(BB * NN * CC) / 1024, 256>>>(x, xr);
    {
        dim3 blk(32, 8);
        transpose_kernel<<<dim3(8, 8, 1), blk>>>(Wq, Wt + 0 * CC * CC, CC, CC, 0, 0);
        transpose_kernel<<<dim3(8, 8, 1), blk>>>(Wk, Wt + 1 * CC * CC, CC, CC, 0, 0);
        transpose_kernel<<<dim3(8, 8, 1), blk>>>(Wv, Wt + 2 * CC * CC, CC, CC, 0, 0);
    }

    // 1) QKV = xr @ Wt^T  (z = projection), outputs tf32-rounded
    mma_abt<true><<<dim3(CC / 128, (BB * NN) / 128, 3), 256, SMEM_SZ>>>(
        xr, Wt, QKV, CC, CC, 1.0f, 0, (long long)CC * CC, QKV_SZ);

    // 2) Vt = transpose(V) per batch -> [C, N]
    {
        dim3 blk(32, 8);
        transpose_kernel<<<dim3(CC / 32, NN / 32, BB), blk>>>(
            QKV + 2 * QKV_SZ, Vt, NN, CC, (long long)NN * CC, (long long)NN * CC);
    }

    // 3) scores_b = Q_b @ K_b^T / 16
    mma_abt<false><<<dim3(NN / 128, NN / 128, BB), 256, SMEM_SZ>>>(
        QKV, QKV + QKV_SZ, scores, CC, NN, 1.0f / 16.0f,
        (long long)NN * CC, (long long)NN * CC, (long long)NN * NN);

    // 4) softmax over batch dim: exact S -> out, rounded S -> scores
    batch_softmax_kernel<<<(NN * NN) / 256, 256>>>(scores, out + OFF_S);

    // 5) Z_b = S_b @ Vt_b^T   (A [1024,1024], B = Vt [256,1024])
    mma_abt<false><<<dim3(CC / 128, NN / 128, BB), 256, SMEM_SZ>>>(
        scores, Vt, out + OFF_Z, NN, CC, 1.0f,
        (long long)NN * NN, (long long)NN * CC, (long long)NN * CC);

    // 6) P
    p_kernel<<<BB * NN, 256>>>(x, Ws, eps, out + OFF_P);
}

// round 5
// speedup vs baseline: 2.7605x; 1.0094x over previous
#include <cuda_runtime.h>
#include <cstdint>

// ---------------------------------------------------------------------------
// AnomalyAttention B=16, N=1024, C=256 — mma.sync tf32, fused rounding,
// zero transpose/round glue passes.
// Outputs: Z [B,N,C] | P [B,N,N] | S [B,N,N]
// ---------------------------------------------------------------------------

#define BB 16
#define NN 1024
#define CC 256

static const long long OFF_Z = 0;
static const long long OFF_P = (long long)BB * NN * CC;
static const long long OFF_S = OFF_P + (long long)BB * NN * NN;

// Scratch (device globals — no runtime allocation allowed)
__device__ float g_QKV[(size_t)3 * BB * NN * CC];     // Q|K|V (tf32-rounded)
__device__ float g_scores[(size_t)BB * NN * NN];      // raw scores

// ---------------------------------------------------------------------------
__device__ __forceinline__ uint32_t smem_u32(const void* p) {
    uint32_t a;
    asm("{ .reg .u64 t; cvta.to.shared.u64 t, %1; cvt.u32.u64 %0, t; }"
        : "=r"(a) : "l"(p));
    return a;
}
__device__ __forceinline__ float tf32r(float x) {
    float y; asm("cvt.rna.tf32.f32 %0, %1;" : "=f"(y) : "f"(x)); return y;
}
__device__ __forceinline__ uint32_t tf32u(uint32_t x) {
    float y = tf32r(__uint_as_float(x)); return __float_as_uint(y);
}

// ---------------------------------------------------------------------------
// mma.sync tf32 GEMM, two B layouts:
//   BNMAJ=false: C = alpha * A * B^T   (B [N,K] K-major, row stride ldb=K)
//   BNMAJ=true : C = alpha * A * B     (B [K,N] N-major, row stride ldb)
// A [M,K] K-major. M,N tiles of 128, K % 32 == 0.
// CTA: 256 threads = 8 warps (2 M x 4 N), warp tile 64x32, BK=32 dbl-buffered.
// RA/RB: round fragments to tf32 (rna) in-register. RO: round output.
// Conflict-free smem: A pad 36 (bank=(4g+t)%32), B N-major pad 136
// (bank=(8t+g)%32), both bijective over the warp.
// ---------------------------------------------------------------------------
template <bool BNMAJ, bool RA, bool RB, bool RO>
__global__ __launch_bounds__(256, 2) void mma_gemm(
    const float* __restrict__ A, const float* __restrict__ B, float* __restrict__ C,
    int K, int ldb, int ldc, float alpha,
    long long sA, long long sB, long long sC)
{
    constexpr int BM = 128, BK = 32, PAD = 36, PADN = 136;
    constexpr int BSTG = BNMAJ ? BK * PADN : BM * PAD;
    extern __shared__ float sm[];
    float* As = sm;                    // [2][BM][PAD]
    float* Bs = sm + 2 * BM * PAD;     // [2][...]

    A += (long long)blockIdx.z * sA;
    B += (long long)blockIdx.z * sB;
    C += (long long)blockIdx.z * sC;

    const int tid = threadIdx.x, lane = tid & 31, wid = tid >> 5;
    const int wm = wid >> 2, wn = wid & 3;          // 2 x 4 warp grid
    const int g = lane >> 2, t = lane & 3;
    const long long arow0 = (long long)blockIdx.y * BM;
    const long long bcol0 = (long long)blockIdx.x * BM;   // N-tile origin

    auto issue = [&](int j) {
        const int abuf = (j & 1) * BM * PAD;
        const int bbuf = (j & 1) * BSTG;
        #pragma unroll
        for (int i = 0; i < 4; i++) {
            const int ch = tid + 256 * i;
            {   // A: 128 rows x 8 chunks (of 4 floats)
                const int row = ch >> 3, c16 = ch & 7;
                const uint32_t da = smem_u32(&As[abuf + row * PAD + c16 * 4]);
                const float* pa = A + (arow0 + row) * K + (long long)j * BK + c16 * 4;
                asm volatile("cp.async.cg.shared.global [%0], [%1], 16;"
                             :: "r"(da), "l"(pa) : "memory");
            }
            if (BNMAJ) {  // B: 32 k-rows x 32 chunks
                const int row = ch >> 5, c4 = (ch & 31) * 4;
                const uint32_t db = smem_u32(&Bs[bbuf + row * PADN + c4]);
                const float* pb = B + ((long long)j * BK + row) * ldb + bcol0 + c4;
                asm volatile("cp.async.cg.shared.global [%0], [%1], 16;"
                             :: "r"(db), "l"(pb) : "memory");
            } else {      // B: 128 n-rows x 8 chunks
                const int row = ch >> 3, c16 = ch & 7;
                const uint32_t db = smem_u32(&Bs[bbuf + row * PAD + c16 * 4]);
                const float* pb = B + (bcol0 + row) * ldb + (long long)j * BK + c16 * 4;
                asm volatile("cp.async.cg.shared.global [%0], [%1], 16;"
                             :: "r"(db), "l"(pb) : "memory");
            }
        }
        asm volatile("cp.async.commit_group;" ::: "memory");
    };

    float acc[4][4][4];
    #pragma unroll
    for (int i = 0; i < 4; i++)
        #pragma unroll
        for (int jn = 0; jn < 4; jn++)
            #pragma unroll
            for (int r = 0; r < 4; r++) acc[i][jn][r] = 0.f;

    const int nch = K / BK;
    issue(0);

    for (int j = 0; j < nch; j++) {
        if (j + 1 < nch) {
            issue(j + 1);
            asm volatile("cp.async.wait_group 1;" ::: "memory");
        } else {
            asm volatile("cp.async.wait_group 0;" ::: "memory");
        }
        __syncthreads();

        const float* a_ = &As[(j & 1) * BM * PAD];
        const float* b_ = &Bs[(j & 1) * BSTG];

        #pragma unroll
        for (int ks = 0; ks < 4; ks++) {
            uint32_t af[4][4], bf[4][2];
            #pragma unroll
            for (int mt = 0; mt < 4; mt++) {
                const int r = wm * 64 + mt * 16 + g;
                const int c = ks * 8 + t;
                af[mt][0] = __float_as_uint(a_[r * PAD + c]);
                af[mt][1] = __float_as_uint(a_[(r + 8) * PAD + c]);
                af[mt][2] = __float_as_uint(a_[r * PAD + c + 4]);
                af[mt][3] = __float_as_uint(a_[(r + 8) * PAD + c + 4]);
                if (RA) {
                    af[mt][0] = tf32u(af[mt][0]); af[mt][1] = tf32u(af[mt][1]);
                    af[mt][2] = tf32u(af[mt][2]); af[mt][3] = tf32u(af[mt][3]);
                }
            }
            #pragma unroll
            for (int nt = 0; nt < 4; nt++) {
                const int n = wn * 32 + nt * 8 + g;
                if (BNMAJ) {
                    bf[nt][0] = __float_as_uint(b_[(ks * 8 + t) * PADN + n]);
                    bf[nt][1] = __float_as_uint(b_[(ks * 8 + t + 4) * PADN + n]);
                } else {
                    bf[nt][0] = __float_as_uint(b_[n * PAD + ks * 8 + t]);
                    bf[nt][1] = __float_as_uint(b_[n * PAD + ks * 8 + t + 4]);
                }
                if (RB) { bf[nt][0] = tf32u(bf[nt][0]); bf[nt][1] = tf32u(bf[nt][1]); }
            }
            #pragma unroll
            for (int mt = 0; mt < 4; mt++)
                #pragma unroll
                for (int nt = 0; nt < 4; nt++)
                    asm volatile(
                        "mma.sync.aligned.m16n8k8.row.col.f32.tf32.tf32.f32 "
                        "{%0,%1,%2,%3}, {%4,%5,%6,%7}, {%8,%9}, {%0,%1,%2,%3};"
                        : "+f"(acc[mt][nt][0]), "+f"(acc[mt][nt][1]),
                          "+f"(acc[mt][nt][2]), "+f"(acc[mt][nt][3])
                        : "r"(af[mt][0]), "r"(af[mt][1]), "r"(af[mt][2]), "r"(af[mt][3]),
                          "r"(bf[nt][0]), "r"(bf[nt][1]));
        }
        __syncthreads();
    }

    // epilogue: c0,c1 at (row g, cols 2t,2t+1); c2,c3 at row g+8
    #pragma unroll
    for (int mt = 0; mt < 4; mt++) {
        const long long gr = arow0 + wm * 64 + mt * 16 + g;
        #pragma unroll
        for (int nt = 0; nt < 4; nt++) {
            const long long gc = bcol0 + wn * 32 + nt * 8 + 2 * t;
            float2 v0 = make_float2(acc[mt][nt][0] * alpha, acc[mt][nt][1] * alpha);
            float2 v1 = make_float2(acc[mt][nt][2] * alpha, acc[mt][nt][3] * alpha);
            if (RO) {
                v0.x = tf32r(v0.x); v0.y = tf32r(v0.y);
                v1.x = tf32r(v1.x); v1.y = tf32r(v1.y);
            }
            *reinterpret_cast<float2*>(&C[gr * ldc + gc])       = v0;
            *reinterpret_cast<float2*>(&C[(gr + 8) * ldc + gc]) = v1;
        }
    }
}

// ---------------------------------------------------------------------------
// softmax over batch dim (axis=0): exact S -> out only
// ---------------------------------------------------------------------------
__global__ __launch_bounds__(256) void batch_softmax_kernel(
    const float* __restrict__ scores, float* __restrict__ S)
{
    size_t idx = (size_t)blockIdx.x * blockDim.x + threadIdx.x;
    float v[BB];
    float mx = -1e30f;
    #pragma unroll
    for (int b = 0; b < BB; b++) {
        v[b] = scores[(size_t)b * NN * NN + idx];
        mx = fmaxf(mx, v[b]);
    }
    float s = 0.f;
    #pragma unroll
    for (int b = 0; b < BB; b++) { v[b] = __expf(v[b] - mx); s += v[b]; }
    const float inv = 1.0f / s;
    #pragma unroll
    for (int b = 0; b < BB; b++)
        S[(size_t)b * NN * NN + idx] = v[b] * inv;
}

// ---------------------------------------------------------------------------
// P kernel (fp32 exact): P[row,m] = (|n-m| + sig*eps)/rowsum
// ---------------------------------------------------------------------------
__global__ __launch_bounds__(256) void p_kernel(
    const float* __restrict__ x, const float* __restrict__ Wsig,
    const float* __restrict__ eps, float* __restrict__ P)
{
    const int row = blockIdx.x;
    const int n = row & (NN - 1);
    const int tid = threadIdx.x;
    __shared__ float red[8];

    float part = x[(size_t)row * CC + tid] * Wsig[tid];
    #pragma unroll
    for (int o = 16; o > 0; o >>= 1) part += __shfl_xor_sync(0xffffffffu, part, o);
    if ((tid & 31) == 0) red[tid >> 5] = part;
    __syncthreads();
    float sig = red[0] + red[1] + red[2] + red[3] + red[4] + red[5] + red[6] + red[7];
    sig = fabsf(sig);
    __syncthreads();

    float4 e = *reinterpret_cast<const float4*>(&eps[(size_t)row * NN + tid * 4]);
    float ps = e.x + e.y + e.z + e.w;
    #pragma unroll
    for (int o = 16; o > 0; o >>= 1) ps += __shfl_xor_sync(0xffffffffu, ps, o);
    if ((tid & 31) == 0) red[tid >> 5] = ps;
    __syncthreads();
    float sum_eps = red[0] + red[1] + red[2] + red[3] + red[4] + red[5] + red[6] + red[7];

    float An = 0.5f * ((float)n * (float)(n + 1) +
                       (float)(NN - 1 - n) * (float)(NN - n));
    float inv = 1.0f / (An + sig * sum_eps);

    int m0 = tid * 4;
    float4 o4;
    o4.x = (fabsf((float)(n - (m0 + 0))) + sig * e.x) * inv;
    o4.y = (fabsf((float)(n - (m0 + 1))) + sig * e.y) * inv;
    o4.z = (fabsf((float)(n - (m0 + 2))) + sig * e.z) * inv;
    o4.w = (fabsf((float)(n - (m0 + 3))) + sig * e.w) * inv;
    *reinterpret_cast<float4*>(&P[(size_t)row * NN + m0]) = o4;
}

// ---------------------------------------------------------------------------
extern "C" void kernel_launch(void* const* d_in, const int* in_sizes, int n_in,
                              void* d_out, int out_size)
{
    const float* x   = (const float*)d_in[0];
    const float* Wq  = (const float*)d_in[1];
    const float* Wk  = (const float*)d_in[2];
    const float* Wv  = (const float*)d_in[3];
    const float* Ws  = (const float*)d_in[4];
    const float* eps = (const float*)d_in[5];
    float* out = (float*)d_out;

    float *QKV, *scores;
    cudaGetSymbolAddress((void**)&QKV, g_QKV);
    cudaGetSymbolAddress((void**)&scores, g_scores);

    const int SMEM_SZ = (2 * 128 * 36 + 2 * 128 * 36) * sizeof(float);  // 73,728
    cudaFuncSetAttribute((void*)mma_gemm<true,  true,  true,  true >,
                         cudaFuncAttributeMaxDynamicSharedMemorySize, SMEM_SZ);
    cudaFuncSetAttribute((void*)mma_gemm<false, false, false, false>,
                         cudaFuncAttributeMaxDynamicSharedMemorySize, SMEM_SZ);
    cudaFuncSetAttribute((void*)mma_gemm<true,  true,  false, false>,
                         cudaFuncAttributeMaxDynamicSharedMemorySize, SMEM_SZ);

    const long long QKV_SZ = (long long)BB * NN * CC;

    // 1) Q/K/V = round(x) @ round(W)  (W consumed N-major; outputs tf32-rounded)
    {
        dim3 grid(CC / 128, (BB * NN) / 128, 1);
        mma_gemm<true, true, true, true><<<grid, 256, SMEM_SZ>>>(
            x, Wq, QKV + 0 * QKV_SZ, CC, CC, CC, 1.0f, 0, 0, 0);
        mma_gemm<true, true, true, true><<<grid, 256, SMEM_SZ>>>(
            x, Wk, QKV + 1 * QKV_SZ, CC, CC, CC, 1.0f, 0, 0, 0);
        mma_gemm<true, true, true, true><<<grid, 256, SMEM_SZ>>>(
            x, Wv, QKV + 2 * QKV_SZ, CC, CC, CC, 1.0f, 0, 0, 0);
    }

    // 2) scores_b = Q_b @ K_b^T / 16   (operands already tf32)
    mma_gemm<false, false, false, false><<<dim3(NN / 128, NN / 128, BB), 256, SMEM_SZ>>>(
        QKV, QKV + QKV_SZ, scores, CC, CC, NN, 1.0f / 16.0f,
        (long long)NN * CC, (long long)NN * CC, (long long)NN * NN);

    // 3) softmax over batch dim: exact S -> out
    batch_softmax_kernel<<<(NN * NN) / 256, 256>>>(scores, out + OFF_S);

    // 4) Z_b = round(S_b) @ V_b   (V consumed N-major, already rounded)
    mma_gemm<true, true, false, false><<<dim3(CC / 128, NN / 128, BB), 256, SMEM_SZ>>>(
        out + OFF_S, QKV + 2 * QKV_SZ, out + OFF_Z, NN, CC, CC, 1.0f,
        (long long)NN * NN, (long long)NN * CC, (long long)NN * CC);

    // 5) P
    p_kernel<<<BB * NN, 256>>>(x, Ws, eps, out + OFF_P);
}

// round 6
// speedup vs baseline: 2.9755x; 1.0779x over previous
#include <cuda_runtime.h>
#include <cstdint>

// ---------------------------------------------------------------------------
// AnomalyAttention B=16, N=1024, C=256 — mma.sync tf32, 64x64 warp tiles,
// 3-stage cp.async ring, fused QKV launch.
// Outputs: Z [B,N,C] | P [B,N,N] | S [B,N,N]
// ---------------------------------------------------------------------------

#define BB 16
#define NN 1024
#define CC 256

static const long long OFF_Z = 0;
static const long long OFF_P = (long long)BB * NN * CC;
static const long long OFF_S = OFF_P + (long long)BB * NN * NN;

__device__ float g_QKV[(size_t)3 * BB * NN * CC];     // Q|K|V (tf32-rounded)
__device__ float g_scores[(size_t)BB * NN * NN];      // raw scores

// ---------------------------------------------------------------------------
__device__ __forceinline__ uint32_t smem_u32(const void* p) {
    uint32_t a;
    asm("{ .reg .u64 t; cvta.to.shared.u64 t, %1; cvt.u32.u64 %0, t; }"
        : "=r"(a) : "l"(p));
    return a;
}
__device__ __forceinline__ float tf32r(float x) {
    float y; asm("cvt.rna.tf32.f32 %0, %1;" : "=f"(y) : "f"(x)); return y;
}
__device__ __forceinline__ uint32_t tf32u(uint32_t x) {
    float y = tf32r(__uint_as_float(x)); return __float_as_uint(y);
}

// ---------------------------------------------------------------------------
// mma.sync tf32 GEMM, CTA tile 128x128, 128 threads = 4 warps (2M x 2N),
// warp tile 64x64, BK=32, 3-stage cp.async ring (one barrier per chunk).
//   BNMAJ=false: C = alpha * A * B^T   (B [N,K] K-major, ldb=K)
//   BNMAJ=true : C = alpha * A * B     (B [K,N] N-major, ldb)
//   MULTIB: B pointer selected from {B0,B1,B2} by blockIdx.z (shared A).
//   RA/RB: round fragments to tf32 (rna) in-register. RO: round outputs.
// Conflict-free smem: A/B K-major pad 36 -> bank (4g+t)%32 bijective;
// B N-major pad 136 -> bank (8t+g)%32 bijective.
// ---------------------------------------------------------------------------
template <bool BNMAJ, bool MULTIB, bool RA, bool RB, bool RO>
__global__ __launch_bounds__(128, 2) void mma_gemm(
    const float* __restrict__ A, const float* __restrict__ B0,
    const float* __restrict__ B1, const float* __restrict__ B2,
    float* __restrict__ C,
    int K, int ldb, int ldc, float alpha,
    long long sA, long long sB, long long sC)
{
    constexpr int BM = 128, BK = 32, PAD = 36, PADN = 136;
    constexpr int ASTG = BM * PAD;                       // floats per A stage
    constexpr int BSTG = BNMAJ ? BK * PADN : BM * PAD;   // floats per B stage
    extern __shared__ float sm[];
    float* As = sm;                  // [3][ASTG]
    float* Bs = sm + 3 * ASTG;       // [3][BSTG]

    const int z = blockIdx.z;
    const float* B = MULTIB ? (z == 0 ? B0 : (z == 1 ? B1 : B2))
                            : B0 + (long long)z * sB;
    A += (long long)z * sA;
    C += (long long)z * sC;

    const int tid = threadIdx.x, lane = tid & 31, wid = tid >> 5;
    const int wm = wid >> 1, wn = wid & 1;               // 2 x 2 warp grid
    const int g = lane >> 2, t = lane & 3;
    const long long arow0 = (long long)blockIdx.y * BM;
    const long long bcol0 = (long long)blockIdx.x * BM;

    const int nch = K / BK;

    auto issue = [&](int j) {
        if (j < nch) {
            const int st = j % 3;
            float* as = As + st * ASTG;
            float* bs = Bs + st * BSTG;
            #pragma unroll
            for (int i = 0; i < 8; i++) {
                const int ch = tid + 128 * i;            // 1024 chunks of 16B
                {   // A: 128 rows x 8 chunks
                    const int row = ch >> 3, c16 = ch & 7;
                    const uint32_t da = smem_u32(&as[row * PAD + c16 * 4]);
                    const float* pa = A + (arow0 + row) * K + (long long)j * BK + c16 * 4;
                    asm volatile("cp.async.cg.shared.global [%0], [%1], 16;"
                                 :: "r"(da), "l"(pa) : "memory");
                }
                if (BNMAJ) {   // B: 32 k-rows x 32 chunks
                    const int row = ch >> 5, c4 = (ch & 31) * 4;
                    const uint32_t db = smem_u32(&bs[row * PADN + c4]);
                    const float* pb = B + ((long long)j * BK + row) * ldb + bcol0 + c4;
                    asm volatile("cp.async.cg.shared.global [%0], [%1], 16;"
                                 :: "r"(db), "l"(pb) : "memory");
                } else {       // B: 128 n-rows x 8 chunks
                    const int row = ch >> 3, c16 = ch & 7;
                    const uint32_t db = smem_u32(&bs[row * PAD + c16 * 4]);
                    const float* pb = B + (bcol0 + row) * ldb + (long long)j * BK + c16 * 4;
                    asm volatile("cp.async.cg.shared.global [%0], [%1], 16;"
                                 :: "r"(db), "l"(pb) : "memory");
                }
            }
        }
        asm volatile("cp.async.commit_group;" ::: "memory");
    };

    float acc[4][8][4];
    #pragma unroll
    for (int i = 0; i < 4; i++)
        #pragma unroll
        for (int jn = 0; jn < 8; jn++)
            #pragma unroll
            for (int r = 0; r < 4; r++) acc[i][jn][r] = 0.f;

    issue(0);
    issue(1);

    for (int j = 0; j < nch; j++) {
        if (j == nch - 1) asm volatile("cp.async.wait_group 0;" ::: "memory");
        else              asm volatile("cp.async.wait_group 1;" ::: "memory");
        __syncthreads();
        issue(j + 2);    // writes stage (j+2)%3 == (j-1)%3 — all warps past it

        const float* a_ = As + (j % 3) * ASTG;
        const float* b_ = Bs + (j % 3) * BSTG;

        #pragma unroll
        for (int ks = 0; ks < 4; ks++) {
            uint32_t af[4][4], bf[8][2];
            #pragma unroll
            for (int mt = 0; mt < 4; mt++) {
                const int r = wm * 64 + mt * 16 + g;
                const int c = ks * 8 + t;
                af[mt][0] = __float_as_uint(a_[r * PAD + c]);
                af[mt][1] = __float_as_uint(a_[(r + 8) * PAD + c]);
                af[mt][2] = __float_as_uint(a_[r * PAD + c + 4]);
                af[mt][3] = __float_as_uint(a_[(r + 8) * PAD + c + 4]);
                if (RA) {
                    af[mt][0] = tf32u(af[mt][0]); af[mt][1] = tf32u(af[mt][1]);
                    af[mt][2] = tf32u(af[mt][2]); af[mt][3] = tf32u(af[mt][3]);
                }
            }
            #pragma unroll
            for (int nt = 0; nt < 8; nt++) {
                const int n = wn * 64 + nt * 8 + g;
                if (BNMAJ) {
                    bf[nt][0] = __float_as_uint(b_[(ks * 8 + t) * PADN + n]);
                    bf[nt][1] = __float_as_uint(b_[(ks * 8 + t + 4) * PADN + n]);
                } else {
                    bf[nt][0] = __float_as_uint(b_[n * PAD + ks * 8 + t]);
                    bf[nt][1] = __float_as_uint(b_[n * PAD + ks * 8 + t + 4]);
                }
                if (RB) { bf[nt][0] = tf32u(bf[nt][0]); bf[nt][1] = tf32u(bf[nt][1]); }
            }
            #pragma unroll
            for (int mt = 0; mt < 4; mt++)
                #pragma unroll
                for (int nt = 0; nt < 8; nt++)
                    asm volatile(
                        "mma.sync.aligned.m16n8k8.row.col.f32.tf32.tf32.f32 "
                        "{%0,%1,%2,%3}, {%4,%5,%6,%7}, {%8,%9}, {%0,%1,%2,%3};"
                        : "+f"(acc[mt][nt][0]), "+f"(acc[mt][nt][1]),
                          "+f"(acc[mt][nt][2]), "+f"(acc[mt][nt][3])
                        : "r"(af[mt][0]), "r"(af[mt][1]), "r"(af[mt][2]), "r"(af[mt][3]),
                          "r"(bf[nt][0]), "r"(bf[nt][1]));
        }
    }

    // epilogue: c0,c1 at (row g, cols 2t,2t+1); c2,c3 at row g+8
    #pragma unroll
    for (int mt = 0; mt < 4; mt++) {
        const long long gr = arow0 + wm * 64 + mt * 16 + g;
        #pragma unroll
        for (int nt = 0; nt < 8; nt++) {
            const long long gc = bcol0 + wn * 64 + nt * 8 + 2 * t;
            float2 v0 = make_float2(acc[mt][nt][0] * alpha, acc[mt][nt][1] * alpha);
            float2 v1 = make_float2(acc[mt][nt][2] * alpha, acc[mt][nt][3] * alpha);
            if (RO) {
                v0.x = tf32r(v0.x); v0.y = tf32r(v0.y);
                v1.x = tf32r(v1.x); v1.y = tf32r(v1.y);
            }
            *reinterpret_cast<float2*>(&C[gr * ldc + gc])       = v0;
            *reinterpret_cast<float2*>(&C[(gr + 8) * ldc + gc]) = v1;
        }
    }
}

// ---------------------------------------------------------------------------
// softmax over batch dim (axis=0): exact S -> out
// ---------------------------------------------------------------------------
__global__ __launch_bounds__(256) void batch_softmax_kernel(
    const float* __restrict__ scores, float* __restrict__ S)
{
    size_t idx = (size_t)blockIdx.x * blockDim.x + threadIdx.x;
    float v[BB];
    float mx = -1e30f;
    #pragma unroll
    for (int b = 0; b < BB; b++) {
        v[b] = scores[(size_t)b * NN * NN + idx];
        mx = fmaxf(mx, v[b]);
    }
    float s = 0.f;
    #pragma unroll
    for (int b = 0; b < BB; b++) { v[b] = __expf(v[b] - mx); s += v[b]; }
    const float inv = 1.0f / s;
    #pragma unroll
    for (int b = 0; b < BB; b++)
        S[(size_t)b * NN * NN + idx] = v[b] * inv;
}

// ---------------------------------------------------------------------------
// P kernel (fp32 exact): P[row,m] = (|n-m| + sig*eps)/rowsum
// ---------------------------------------------------------------------------
__global__ __launch_bounds__(256) void p_kernel(
    const float* __restrict__ x, const float* __restrict__ Wsig,
    const float* __restrict__ eps, float* __restrict__ P)
{
    const int row = blockIdx.x;
    const int n = row & (NN - 1);
    const int tid = threadIdx.x;
    __shared__ float red[8];

    float part = x[(size_t)row * CC + tid] * Wsig[tid];
    #pragma unroll
    for (int o = 16; o > 0; o >>= 1) part += __shfl_xor_sync(0xffffffffu, part, o);
    if ((tid & 31) == 0) red[tid >> 5] = part;
    __syncthreads();
    float sig = red[0] + red[1] + red[2] + red[3] + red[4] + red[5] + red[6] + red[7];
    sig = fabsf(sig);
    __syncthreads();

    float4 e = *reinterpret_cast<const float4*>(&eps[(size_t)row * NN + tid * 4]);
    float ps = e.x + e.y + e.z + e.w;
    #pragma unroll
    for (int o = 16; o > 0; o >>= 1) ps += __shfl_xor_sync(0xffffffffu, ps, o);
    if ((tid & 31) == 0) red[tid >> 5] = ps;
    __syncthreads();
    float sum_eps = red[0] + red[1] + red[2] + red[3] + red[4] + red[5] + red[6] + red[7];

    float An = 0.5f * ((float)n * (float)(n + 1) +
                       (float)(NN - 1 - n) * (float)(NN - n));
    float inv = 1.0f / (An + sig * sum_eps);

    int m0 = tid * 4;
    float4 o4;
    o4.x = (fabsf((float)(n - (m0 + 0))) + sig * e.x) * inv;
    o4.y = (fabsf((float)(n - (m0 + 1))) + sig * e.y) * inv;
    o4.z = (fabsf((float)(n - (m0 + 2))) + sig * e.z) * inv;
    o4.w = (fabsf((float)(n - (m0 + 3))) + sig * e.w) * inv;
    *reinterpret_cast<float4*>(&P[(size_t)row * NN + m0]) = o4;
}

// ---------------------------------------------------------------------------
extern "C" void kernel_launch(void* const* d_in, const int* in_sizes, int n_in,
                              void* d_out, int out_size)
{
    const float* x   = (const float*)d_in[0];
    const float* Wq  = (const float*)d_in[1];
    const float* Wk  = (const float*)d_in[2];
    const float* Wv  = (const float*)d_in[3];
    const float* Ws  = (const float*)d_in[4];
    const float* eps = (const float*)d_in[5];
    float* out = (float*)d_out;

    float *QKV, *scores;
    cudaGetSymbolAddress((void**)&QKV, g_QKV);
    cudaGetSymbolAddress((void**)&scores, g_scores);

    // smem: 3 stages; A stage 128*36, B stage N-major 32*136 else 128*36
    const int SMEM_NMAJ = (3 * 128 * 36 + 3 * 32 * 136) * sizeof(float);  // 107,520
    const int SMEM_KMAJ = (3 * 128 * 36 * 2) * sizeof(float);             // 110,592
    cudaFuncSetAttribute((void*)mma_gemm<true,  true,  true,  true,  true >,
                         cudaFuncAttributeMaxDynamicSharedMemorySize, SMEM_NMAJ);
    cudaFuncSetAttribute((void*)mma_gemm<false, false, false, false, false>,
                         cudaFuncAttributeMaxDynamicSharedMemorySize, SMEM_KMAJ);
    cudaFuncSetAttribute((void*)mma_gemm<true,  false, true,  false, false>,
                         cudaFuncAttributeMaxDynamicSharedMemorySize, SMEM_NMAJ);

    const long long QKV_SZ = (long long)BB * NN * CC;

    // 1) Q/K/V = round(x) @ round(W) — one launch, z picks the projection
    mma_gemm<true, true, true, true, true>
        <<<dim3(CC / 128, (BB * NN) / 128, 3), 128, SMEM_NMAJ>>>(
        x, Wq, Wk, Wv, QKV, CC, CC, CC, 1.0f, 0, 0, QKV_SZ);

    // 2) scores_b = Q_b @ K_b^T / 16  (operands already tf32)
    mma_gemm<false, false, false, false, false>
        <<<dim3(NN / 128, NN / 128, BB), 128, SMEM_KMAJ>>>(
        QKV, QKV + QKV_SZ, nullptr, nullptr, scores, CC, CC, NN, 1.0f / 16.0f,
        (long long)NN * CC, (long long)NN * CC, (long long)NN * NN);

    // 3) softmax over batch dim: exact S -> out
    batch_softmax_kernel<<<(NN * NN) / 256, 256>>>(scores, out + OFF_S);

    // 4) Z_b = round(S_b) @ V_b  (V consumed N-major, already rounded)
    mma_gemm<true, false, true, false, false>
        <<<dim3(CC / 128, NN / 128, BB), 128, SMEM_NMAJ>>>(
        out + OFF_S, QKV + 2 * QKV_SZ, nullptr, nullptr, out + OFF_Z,
        NN, CC, CC, 1.0f,
        (long long)NN * NN, (long long)NN * CC, (long long)NN * CC);

    // 5) P
    p_kernel<<<BB * NN, 256>>>(x, Ws, eps, out + OFF_P);
}